// round 1
// baseline (speedup 1.0000x reference)
#include <cuda_runtime.h>
#include <stdint.h>

#define EPSF 1e-6f

#define NB 32
#define NS 8
#define HW 65536
#define NACC 66
// per-batch accumulator layout:
//   [0..48]  fg inter[p*7+g]  (pred slot p+1, gt slot g+1)
//   [49..56] sum_pred[s] for s=0..7
//   [57..64] sum_gt[s]   for s=0..7
//   [65]     bg inter (slot0 * slot0)

__device__ float g_acc[NB][NACC];

__global__ void zero_kernel() {
    int i = blockIdx.x * blockDim.x + threadIdx.x;
    if (i < NB * NACC) ((float*)g_acc)[i] = 0.0f;
}

__device__ __forceinline__ float warp_sum(float v) {
    #pragma unroll
    for (int off = 16; off > 0; off >>= 1)
        v += __shfl_down_sync(0xffffffffu, v, off);
    return v;
}

#define NCHUNK 16
#define TPB 256

__global__ __launch_bounds__(TPB, 2)
void accum_kernel(const float* __restrict__ pred, const float* __restrict__ gt) {
    const int b = blockIdx.x / NCHUNK;
    const int chunk = blockIdx.x % NCHUNK;
    const int cbase = chunk * (HW / NCHUNK);

    const float* __restrict__ pb = pred + (size_t)b * NS * HW;
    const float* __restrict__ gb = gt   + (size_t)b * NS * HW;

    float inter[49];
    float sp[8], sg[8];
    float bgi = 0.0f;
    #pragma unroll
    for (int k = 0; k < 49; k++) inter[k] = 0.0f;
    #pragma unroll
    for (int s = 0; s < 8; s++) { sp[s] = 0.0f; sg[s] = 0.0f; }

    const int cend = cbase + HW / NCHUNK;
    for (int pix = cbase + threadIdx.x; pix < cend; pix += TPB) {
        float p[8], g[8];
        #pragma unroll
        for (int s = 0; s < 8; s++) {
            p[s] = pb[s * HW + pix];
            g[s] = gb[s * HW + pix];
        }
        #pragma unroll
        for (int s = 0; s < 8; s++) { sp[s] += p[s]; sg[s] += g[s]; }
        bgi = fmaf(p[0], g[0], bgi);
        #pragma unroll
        for (int i = 0; i < 7; i++)
            #pragma unroll
            for (int j = 0; j < 7; j++)
                inter[i * 7 + j] = fmaf(p[i + 1], g[j + 1], inter[i * 7 + j]);
    }

    // warp reduce + atomic accumulate
    const int lane = threadIdx.x & 31;
    #pragma unroll
    for (int k = 0; k < 49; k++) {
        float v = warp_sum(inter[k]);
        if (lane == 0) atomicAdd(&g_acc[b][k], v);
    }
    #pragma unroll
    for (int s = 0; s < 8; s++) {
        float v = warp_sum(sp[s]);
        if (lane == 0) atomicAdd(&g_acc[b][49 + s], v);
    }
    #pragma unroll
    for (int s = 0; s < 8; s++) {
        float v = warp_sum(sg[s]);
        if (lane == 0) atomicAdd(&g_acc[b][57 + s], v);
    }
    {
        float v = warp_sum(bgi);
        if (lane == 0) atomicAdd(&g_acc[b][65], v);
    }
}

// Hungarian (Kuhn-Munkres with potentials), rows = n gt objects (n <= 7),
// cols = 7 pred slots. cost[i][j] = -dice[j][i]. Returns sum of matched dice.
__device__ float hungarian_matched_dice_sum(const float dice[7][7], int n) {
    const int m = 7;
    const double INF = 1e18;
    double u[8], v[8];
    int p[8], way[8];
    #pragma unroll
    for (int j = 0; j <= 7; j++) { u[j] = 0.0; v[j] = 0.0; p[j] = 0; way[j] = 0; }

    for (int i = 1; i <= n; i++) {
        p[0] = i;
        int j0 = 0;
        double minv[8];
        bool used[8];
        for (int j = 0; j <= m; j++) { minv[j] = INF; used[j] = false; }
        while (true) {
            used[j0] = true;
            const int i0 = p[j0];
            int j1 = 0;
            double delta = INF;
            for (int j = 1; j <= m; j++) {
                if (!used[j]) {
                    double cur = -(double)dice[j - 1][i0 - 1] - u[i0] - v[j];
                    if (cur < minv[j]) { minv[j] = cur; way[j] = j0; }
                    if (minv[j] < delta) { delta = minv[j]; j1 = j; }
                }
            }
            for (int j = 0; j <= m; j++) {
                if (used[j]) { u[p[j]] += delta; v[j] -= delta; }
                else         { minv[j] -= delta; }
            }
            j0 = j1;
            if (p[j0] == 0) break;
        }
        while (j0) { int j1 = way[j0]; p[j0] = p[j1]; j0 = j1; }
    }

    float s = 0.0f;
    for (int j = 1; j <= m; j++)
        if (p[j] != 0) s += dice[j - 1][p[j] - 1];
    return s;
}

__global__ void finalize_kernel(const int* __restrict__ num_objects,
                                float* __restrict__ out) {
    const int b = threadIdx.x;  // 32 threads, one per batch

    float bg_term = 0.0f;
    float fg_sum = 0.0f;
    int cnt = 0;

    if (b < NB) {
        const float* a = g_acc[b];
        // background dice loss term
        const float bg_inter = a[65];
        const float bsp = a[49];
        const float bsg = a[57];
        bg_term = 1.0f - (2.0f * bg_inter + EPSF) / (bsp + bsg + EPSF);

        // fg dice matrix (pred slot p+1 vs gt slot g+1)
        float dice[7][7];
        #pragma unroll
        for (int p = 0; p < 7; p++)
            #pragma unroll
            for (int g = 0; g < 7; g++)
                dice[p][g] = (2.0f * a[p * 7 + g] + EPSF) /
                             (a[49 + 1 + p] + a[57 + 1 + g] + EPSF);

        int n = num_objects[b];
        if (n > 7) n = 7;
        if (n > 0) {
            float md = hungarian_matched_dice_sum(dice, n);
            fg_sum = (float)n - md;  // sum of (1 - dice) over matched pairs
            cnt = n;
        }
    }

    // reduce across the warp
    #pragma unroll
    for (int off = 16; off > 0; off >>= 1) {
        bg_term += __shfl_down_sync(0xffffffffu, bg_term, off);
        fg_sum  += __shfl_down_sync(0xffffffffu, fg_sum, off);
        cnt     += __shfl_down_sync(0xffffffffu, cnt, off);
    }

    if (threadIdx.x == 0) {
        float bg_loss = bg_term / (float)NB;
        float fg_loss = (cnt > 0) ? (fg_sum / (float)cnt) : 0.0f;
        out[0] = bg_loss + fg_loss;
    }
}

extern "C" void kernel_launch(void* const* d_in, const int* in_sizes, int n_in,
                              void* d_out, int out_size) {
    const float* pred = (const float*)d_in[0];
    const float* gt   = (const float*)d_in[1];
    const int*   nobj = (const int*)d_in[2];
    float* out = (float*)d_out;

    zero_kernel<<<(NB * NACC + 255) / 256, 256>>>();
    accum_kernel<<<NB * NCHUNK, TPB>>>(pred, gt);
    finalize_kernel<<<1, 32>>>(nobj, out);
}

// round 2
// speedup vs baseline: 1.5730x; 1.5730x over previous
#include <cuda_runtime.h>
#include <stdint.h>

#define EPSF 1e-6f

#define NB 32
#define NS 8
#define HW 65536
#define NACC 66
// per-batch accumulator layout:
//   [0..48]  fg inter[p*7+g]  (pred slot p+1, gt slot g+1)
//   [49..56] sum_pred[s] for s=0..7
//   [57..64] sum_gt[s]   for s=0..7
//   [65]     bg inter (slot0 * slot0)

__device__ float g_acc[NB][NACC];

__global__ void zero_kernel() {
    int i = blockIdx.x * blockDim.x + threadIdx.x;
    if (i < NB * NACC) ((float*)g_acc)[i] = 0.0f;
}

__device__ __forceinline__ float warp_sum(float v) {
    #pragma unroll
    for (int off = 16; off > 0; off >>= 1)
        v += __shfl_down_sync(0xffffffffu, v, off);
    return v;
}

#define NCHUNK 32
#define TPB 128

__global__ __launch_bounds__(TPB, 3)
void accum_kernel(const float* __restrict__ pred, const float* __restrict__ gt) {
    const int b = blockIdx.x / NCHUNK;
    const int chunk = blockIdx.x % NCHUNK;
    const int cbase = chunk * (HW / NCHUNK);

    const float* __restrict__ pb = pred + (size_t)b * NS * HW;
    const float* __restrict__ gb = gt   + (size_t)b * NS * HW;

    float inter[49];
    float sp[8], sg[8];
    float bgi = 0.0f;
    #pragma unroll
    for (int k = 0; k < 49; k++) inter[k] = 0.0f;
    #pragma unroll
    for (int s = 0; s < 8; s++) { sp[s] = 0.0f; sg[s] = 0.0f; }

    const int cend = cbase + HW / NCHUNK;
    for (int pix = cbase + threadIdx.x; pix < cend; pix += TPB) {
        float p[8], g[8];
        #pragma unroll
        for (int s = 0; s < 8; s++) {
            p[s] = __ldg(&pb[s * HW + pix]);
            g[s] = __ldg(&gb[s * HW + pix]);
        }
        #pragma unroll
        for (int s = 0; s < 8; s++) { sp[s] += p[s]; sg[s] += g[s]; }
        bgi = fmaf(p[0], g[0], bgi);
        #pragma unroll
        for (int i = 0; i < 7; i++)
            #pragma unroll
            for (int j = 0; j < 7; j++)
                inter[i * 7 + j] = fmaf(p[i + 1], g[j + 1], inter[i * 7 + j]);
    }

    // warp reduce + atomic accumulate
    const int lane = threadIdx.x & 31;
    #pragma unroll
    for (int k = 0; k < 49; k++) {
        float v = warp_sum(inter[k]);
        if (lane == 0) atomicAdd(&g_acc[b][k], v);
    }
    #pragma unroll
    for (int s = 0; s < 8; s++) {
        float v = warp_sum(sp[s]);
        if (lane == 0) atomicAdd(&g_acc[b][49 + s], v);
    }
    #pragma unroll
    for (int s = 0; s < 8; s++) {
        float v = warp_sum(sg[s]);
        if (lane == 0) atomicAdd(&g_acc[b][57 + s], v);
    }
    {
        float v = warp_sum(bgi);
        if (lane == 0) atomicAdd(&g_acc[b][65], v);
    }
}

// Hungarian (Kuhn-Munkres with potentials) in fp32. Rows = n gt objects
// (n <= 7), cols = 7 pred slots. cost[i][j] = -dice[j][i]. Matching only
// needs the argmin structure, so fp32 is sufficient (ties -> same sum).
__device__ float hungarian_matched_dice_sum(const float dice[7][7], int n) {
    const int m = 7;
    const float INF = 1e30f;
    float u[8], v[8];
    int p[8], way[8];
    #pragma unroll
    for (int j = 0; j <= 7; j++) { u[j] = 0.0f; v[j] = 0.0f; p[j] = 0; way[j] = 0; }

    for (int i = 1; i <= n; i++) {
        p[0] = i;
        int j0 = 0;
        float minv[8];
        bool used[8];
        for (int j = 0; j <= m; j++) { minv[j] = INF; used[j] = false; }
        while (true) {
            used[j0] = true;
            const int i0 = p[j0];
            int j1 = 0;
            float delta = INF;
            for (int j = 1; j <= m; j++) {
                if (!used[j]) {
                    float cur = -dice[j - 1][i0 - 1] - u[i0] - v[j];
                    if (cur < minv[j]) { minv[j] = cur; way[j] = j0; }
                    if (minv[j] < delta) { delta = minv[j]; j1 = j; }
                }
            }
            for (int j = 0; j <= m; j++) {
                if (used[j]) { u[p[j]] += delta; v[j] -= delta; }
                else         { minv[j] -= delta; }
            }
            j0 = j1;
            if (p[j0] == 0) break;
        }
        while (j0) { int j1 = way[j0]; p[j0] = p[j1]; j0 = j1; }
    }

    float s = 0.0f;
    for (int j = 1; j <= m; j++)
        if (p[j] != 0) s += dice[j - 1][p[j] - 1];
    return s;
}

__global__ void finalize_kernel(const int* __restrict__ num_objects,
                                float* __restrict__ out) {
    const int b = threadIdx.x;  // 32 threads, one per batch

    float bg_term = 0.0f;
    float fg_sum = 0.0f;
    int cnt = 0;

    if (b < NB) {
        const float* a = g_acc[b];
        // background dice loss term
        const float bg_inter = a[65];
        const float bsp = a[49];
        const float bsg = a[57];
        bg_term = 1.0f - (2.0f * bg_inter + EPSF) / (bsp + bsg + EPSF);

        // fg dice matrix (pred slot p+1 vs gt slot g+1)
        float dice[7][7];
        #pragma unroll
        for (int p = 0; p < 7; p++)
            #pragma unroll
            for (int g = 0; g < 7; g++)
                dice[p][g] = (2.0f * a[p * 7 + g] + EPSF) /
                             (a[49 + 1 + p] + a[57 + 1 + g] + EPSF);

        int n = num_objects[b];
        if (n > 7) n = 7;
        if (n > 0) {
            float md = hungarian_matched_dice_sum(dice, n);
            fg_sum = (float)n - md;  // sum of (1 - dice) over matched pairs
            cnt = n;
        }
    }

    // reduce across the warp
    #pragma unroll
    for (int off = 16; off > 0; off >>= 1) {
        bg_term += __shfl_down_sync(0xffffffffu, bg_term, off);
        fg_sum  += __shfl_down_sync(0xffffffffu, fg_sum, off);
        cnt     += __shfl_down_sync(0xffffffffu, cnt, off);
    }

    if (threadIdx.x == 0) {
        float bg_loss = bg_term / (float)NB;
        float fg_loss = (cnt > 0) ? (fg_sum / (float)cnt) : 0.0f;
        out[0] = bg_loss + fg_loss;
    }
}

extern "C" void kernel_launch(void* const* d_in, const int* in_sizes, int n_in,
                              void* d_out, int out_size) {
    const float* pred = (const float*)d_in[0];
    const float* gt   = (const float*)d_in[1];
    const int*   nobj = (const int*)d_in[2];
    float* out = (float*)d_out;

    zero_kernel<<<(NB * NACC + 255) / 256, 256>>>();
    accum_kernel<<<NB * NCHUNK, TPB>>>(pred, gt);
    finalize_kernel<<<1, 32>>>(nobj, out);
}

// round 5
// speedup vs baseline: 3.4096x; 2.1676x over previous
#include <cuda_runtime.h>
#include <stdint.h>

#define EPSF 1e-6f

#define NB 32
#define NS 8
#define HW 65536
#define HW2 (HW / 2)
#define NACC 66
// per-batch accumulator layout:
//   [0..48]  fg inter[p*7+g]  (pred slot p+1, gt slot g+1)
//   [49..56] sum_pred[s] for s=0..7
//   [57..64] sum_gt[s]   for s=0..7
//   [65]     bg inter (slot0 * slot0)

#define NCHUNK 16
#define TPB 128

__device__ float g_part[NB][NCHUNK][NACC];

__device__ __forceinline__ float warp_sum(float v) {
    #pragma unroll
    for (int off = 16; off > 0; off >>= 1)
        v += __shfl_down_sync(0xffffffffu, v, off);
    return v;
}

__global__ __launch_bounds__(TPB, 3)
void accum_kernel(const float* __restrict__ pred, const float* __restrict__ gt) {
    const int b = blockIdx.x / NCHUNK;
    const int chunk = blockIdx.x % NCHUNK;
    const int cbase = chunk * (HW2 / NCHUNK);   // in float2 units

    const float2* __restrict__ pb = (const float2*)(pred + (size_t)b * NS * HW);
    const float2* __restrict__ gb = (const float2*)(gt   + (size_t)b * NS * HW);

    float inter[49];
    float sp[8], sg[8];
    float bgi = 0.0f;
    #pragma unroll
    for (int k = 0; k < 49; k++) inter[k] = 0.0f;
    #pragma unroll
    for (int s = 0; s < 8; s++) { sp[s] = 0.0f; sg[s] = 0.0f; }

    const int cend = cbase + HW2 / NCHUNK;
    for (int pix = cbase + threadIdx.x; pix < cend; pix += TPB) {
        float2 p[8], g[8];
        #pragma unroll
        for (int s = 0; s < 8; s++) {
            p[s] = pb[s * HW2 + pix];
            g[s] = gb[s * HW2 + pix];
        }
        #pragma unroll
        for (int s = 0; s < 8; s++) {
            sp[s] += p[s].x + p[s].y;
            sg[s] += g[s].x + g[s].y;
        }
        bgi = fmaf(p[0].x, g[0].x, bgi);
        bgi = fmaf(p[0].y, g[0].y, bgi);
        #pragma unroll
        for (int i = 0; i < 7; i++)
            #pragma unroll
            for (int j = 0; j < 7; j++) {
                float acc = inter[i * 7 + j];
                acc = fmaf(p[i + 1].x, g[j + 1].x, acc);
                acc = fmaf(p[i + 1].y, g[j + 1].y, acc);
                inter[i * 7 + j] = acc;
            }
    }

    // warp reduce -> smem -> per-chunk partial write (no atomics)
    __shared__ float wsum[TPB / 32][NACC];
    const int wid = threadIdx.x >> 5;
    const int lane = threadIdx.x & 31;

    #pragma unroll
    for (int k = 0; k < 49; k++) {
        float v = warp_sum(inter[k]);
        if (lane == 0) wsum[wid][k] = v;
    }
    #pragma unroll
    for (int s = 0; s < 8; s++) {
        float v = warp_sum(sp[s]);
        if (lane == 0) wsum[wid][49 + s] = v;
    }
    #pragma unroll
    for (int s = 0; s < 8; s++) {
        float v = warp_sum(sg[s]);
        if (lane == 0) wsum[wid][57 + s] = v;
    }
    {
        float v = warp_sum(bgi);
        if (lane == 0) wsum[wid][65] = v;
    }
    __syncthreads();
    if (threadIdx.x < NACC) {
        float v = 0.0f;
        #pragma unroll
        for (int w = 0; w < TPB / 32; w++) v += wsum[w][threadIdx.x];
        g_part[b][chunk][threadIdx.x] = v;
    }
}

// Single-block finalize: warp w handles batch w.
// Optimal assignment via subset DP over the 7 pred slots (exact, same sum as
// Hungarian): dp[S] = best sum of dice assigning gt objects 0..popc(S)-1 to
// the pred-slot set S. All state in shared memory, lanes parallel over S.
__global__ __launch_bounds__(1024, 1)
void finalize_kernel(const int* __restrict__ num_objects,
                     float* __restrict__ out) {
    __shared__ float a_sm[NB][NACC];
    __shared__ float dice_sm[NB][49];
    __shared__ float dp_sm[NB][128];
    __shared__ float res_bg[NB];
    __shared__ float res_fg[NB];
    __shared__ int   res_n[NB];

    const int w = threadIdx.x >> 5;    // batch
    const int lane = threadIdx.x & 31;

    // phase 1: reduce per-chunk partials
    for (int k = lane; k < NACC; k += 32) {
        float v = 0.0f;
        #pragma unroll
        for (int c = 0; c < NCHUNK; c++) v += g_part[w][c][k];
        a_sm[w][k] = v;
    }
    __syncwarp();

    // phase 2: dice matrix (pred p, gt g) — ALL 49 entries (strided over lanes)
    for (int idx = lane; idx < 49; idx += 32) {
        int p = idx / 7, g = idx % 7;
        dice_sm[w][idx] = (2.0f * a_sm[w][idx] + EPSF) /
                          (a_sm[w][50 + p] + a_sm[w][58 + g] + EPSF);
    }
    __syncwarp();

    int n = num_objects[w];
    if (n > 7) n = 7;
    if (n < 0) n = 0;

    // phase 3: subset DP
    #pragma unroll
    for (int q = 0; q < 4; q++) {
        int S = lane + 32 * q;
        dp_sm[w][S] = (S == 0) ? 0.0f : -1e30f;
    }
    __syncwarp();

    for (int k = 1; k <= n; k++) {
        float newv[4];
        #pragma unroll
        for (int q = 0; q < 4; q++) {
            int S = lane + 32 * q;
            float best = -1e30f;
            if (__popc(S) == k) {
                #pragma unroll
                for (int j = 0; j < 7; j++) {
                    if (S & (1 << j)) {
                        float cand = dp_sm[w][S & ~(1 << j)] + dice_sm[w][j * 7 + (k - 1)];
                        best = fmaxf(best, cand);
                    }
                }
            }
            newv[q] = best;
        }
        __syncwarp();
        #pragma unroll
        for (int q = 0; q < 4; q++) {
            int S = lane + 32 * q;
            if (__popc(S) == k) dp_sm[w][S] = newv[q];
        }
        __syncwarp();
    }

    // best over |S| == n
    float best = -1e30f;
    #pragma unroll
    for (int q = 0; q < 4; q++) {
        int S = lane + 32 * q;
        if (__popc(S) == n) best = fmaxf(best, dp_sm[w][S]);
    }
    #pragma unroll
    for (int off = 16; off > 0; off >>= 1)
        best = fmaxf(best, __shfl_down_sync(0xffffffffu, best, off));

    if (lane == 0) {
        float bg = 1.0f - (2.0f * a_sm[w][65] + EPSF) /
                          (a_sm[w][49] + a_sm[w][57] + EPSF);
        res_bg[w] = bg;
        res_fg[w] = (n > 0) ? ((float)n - best) : 0.0f;
        res_n[w]  = n;
    }
    __syncthreads();

    if (threadIdx.x < 32) {
        float bg = res_bg[threadIdx.x];
        float fg = res_fg[threadIdx.x];
        int   cn = res_n[threadIdx.x];
        #pragma unroll
        for (int off = 16; off > 0; off >>= 1) {
            bg += __shfl_down_sync(0xffffffffu, bg, off);
            fg += __shfl_down_sync(0xffffffffu, fg, off);
            cn += __shfl_down_sync(0xffffffffu, cn, off);
        }
        if (threadIdx.x == 0) {
            float bg_loss = bg / (float)NB;
            float fg_loss = (cn > 0) ? (fg / (float)cn) : 0.0f;
            out[0] = bg_loss + fg_loss;
        }
    }
}

extern "C" void kernel_launch(void* const* d_in, const int* in_sizes, int n_in,
                              void* d_out, int out_size) {
    const float* pred = (const float*)d_in[0];
    const float* gt   = (const float*)d_in[1];
    const int*   nobj = (const int*)d_in[2];
    float* out = (float*)d_out;

    accum_kernel<<<NB * NCHUNK, TPB>>>(pred, gt);
    finalize_kernel<<<1, 1024>>>(nobj, out);
}